// round 11
// baseline (speedup 1.0000x reference)
#include <cuda_runtime.h>

// Resampling: 3D affine grid-sample, trilinear, fp32.
// fmap (B=16,P=8,H=32,W=32,D=32,C=8), theta (B,12*P).
//
// 2 lanes per voxel, split by CHANNEL HALF (chalf = gid&1), 16 voxels/warp.
// Per (y,x) corner each lane loads z0 and z1 float4s (32B apart -> usually
// one 128B line); accumulates both z partials locally; z-blend is in-lane
// FMA (no shuffles). 2x transform-math replication only. Full-warp
// coalesced float4 store at out[gid]. All 8 loads front-batched (MLP=8).

#define RS_B 16
#define RS_P 8
#define RS_H 32
#define RS_W 32
#define RS_D 32
#define RS_C 8
#define RS_VOX (RS_H * RS_W * RS_D)   // 32768 voxels per (b,p) slice

__global__ __launch_bounds__(256) void resample_kernel(
    const float* __restrict__ fmap,
    const float* __restrict__ theta,
    float* __restrict__ out)
{
    __shared__ float t[12];

    const int gid   = blockIdx.x * 256 + threadIdx.x;
    const int voxel = gid >> 1;                 // global voxel id
    const int chalf = gid & 1;                  // which float4 channel half

    const int slice = voxel >> 15;              // b*P + p
    const int n     = voxel & (RS_VOX - 1);

    // theta row: b*96 + p*12 floats — block covers 128 voxels, one slice
    if (threadIdx.x < 12) {
        const int bslice = (blockIdx.x * 128) >> 15;
        t[threadIdx.x] = theta[(bslice >> 3) * (12 * RS_P)
                               + (bslice & (RS_P - 1)) * 12 + threadIdx.x];
    }
    __syncthreads();

    // n = (h*W + w)*D + d ; grid point is (xs[w], ys[h], zs[d])
    const int h = n >> 10;
    const int w = (n >> 5) & 31;
    const int d = n & 31;

    const float step = 2.0f / 31.0f;
    const float gx = fmaf((float)w, step, -1.0f);
    const float gy = fmaf((float)h, step, -1.0f);
    const float gz = fmaf((float)d, step, -1.0f);

    const float xp = t[0] * gx + t[1] * gy + t[2]  * gz + t[3];
    const float yp = t[4] * gx + t[5] * gy + t[6]  * gz + t[7];
    const float zp = t[8] * gx + t[9] * gy + t[10] * gz + t[11];

    const float x = 0.5f * (xp + 1.0f) * (float)(RS_W - 2);
    const float y = 0.5f * (yp + 1.0f) * (float)(RS_H - 2);
    const float z = 0.5f * (zp + 1.0f) * (float)(RS_D - 2);

    int x0 = (int)floorf(x); int x1 = x0 + 1;
    int y0 = (int)floorf(y); int y1 = y0 + 1;
    int z0 = (int)floorf(z); int z1 = z0 + 1;
    x0 = min(max(x0, 0), RS_W - 1); x1 = min(max(x1, 0), RS_W - 1);
    y0 = min(max(y0, 0), RS_H - 1); y1 = min(max(y1, 0), RS_H - 1);
    z0 = min(max(z0, 0), RS_D - 1); z1 = min(max(z1, 0), RS_D - 1);

    // weights from CLAMPED corners (reference semantics)
    const float xd = x - (float)x0;        // weight x1; (1-xd) x0
    const float yd = (float)y1 - y;        // weight y0; (1-yd) y1
    const float zd = z - (float)z0;        // weight z1; (1-zd) z0

    const float wx0 = 1.0f - xd, wx1 = xd;
    const float wy0 = yd,        wy1 = 1.0f - yd;
    const float wz0 = 1.0f - zd, wz1 = zd;

    // lane base: this chalf's float4 at z0 within each corner row
    const float* base = fmap + (size_t)slice * (RS_VOX * RS_C)
                             + (size_t)z0 * RS_C + (size_t)chalf * 4;
    const int dz = (z1 - z0) * 2;          // float4 step to z1 (0 or 2)

    const float w00 = wy0 * wx0;
    const float w01 = wy0 * wx1;
    const float w10 = wy1 * wx0;
    const float w11 = wy1 * wx1;

    const int r00 = (y0 * RS_W + x0) * (RS_D * RS_C);
    const int r01 = (y0 * RS_W + x1) * (RS_D * RS_C);
    const int r10 = (y1 * RS_W + x0) * (RS_D * RS_C);
    const int r11 = (y1 * RS_W + x1) * (RS_D * RS_C);

    const float4* p00 = (const float4*)(base + r00);
    const float4* p01 = (const float4*)(base + r01);
    const float4* p10 = (const float4*)(base + r10);
    const float4* p11 = (const float4*)(base + r11);

    // front-batched loads: z0 and z1 float4 per corner (MLP = 8)
    const float4 a00 = __ldg(p00), b00 = __ldg(p00 + dz);
    const float4 a01 = __ldg(p01), b01 = __ldg(p01 + dz);
    const float4 a10 = __ldg(p10), b10 = __ldg(p10 + dz);
    const float4 a11 = __ldg(p11), b11 = __ldg(p11 + dz);

    float4 az, bz;   // accumulators for z0 and z1 planes
    az.x = w00 * a00.x; az.y = w00 * a00.y; az.z = w00 * a00.z; az.w = w00 * a00.w;
    bz.x = w00 * b00.x; bz.y = w00 * b00.y; bz.z = w00 * b00.z; bz.w = w00 * b00.w;

    az.x = fmaf(w01, a01.x, az.x); az.y = fmaf(w01, a01.y, az.y);
    az.z = fmaf(w01, a01.z, az.z); az.w = fmaf(w01, a01.w, az.w);
    bz.x = fmaf(w01, b01.x, bz.x); bz.y = fmaf(w01, b01.y, bz.y);
    bz.z = fmaf(w01, b01.z, bz.z); bz.w = fmaf(w01, b01.w, bz.w);

    az.x = fmaf(w10, a10.x, az.x); az.y = fmaf(w10, a10.y, az.y);
    az.z = fmaf(w10, a10.z, az.z); az.w = fmaf(w10, a10.w, az.w);
    bz.x = fmaf(w10, b10.x, bz.x); bz.y = fmaf(w10, b10.y, bz.y);
    bz.z = fmaf(w10, b10.z, bz.z); bz.w = fmaf(w10, b10.w, bz.w);

    az.x = fmaf(w11, a11.x, az.x); az.y = fmaf(w11, a11.y, az.y);
    az.z = fmaf(w11, a11.z, az.z); az.w = fmaf(w11, a11.w, az.w);
    bz.x = fmaf(w11, b11.x, bz.x); bz.y = fmaf(w11, b11.y, bz.y);
    bz.z = fmaf(w11, b11.z, bz.z); bz.w = fmaf(w11, b11.w, bz.w);

    // z-blend in-lane (no shuffles)
    float4 r;
    r.x = fmaf(wz0, az.x, wz1 * bz.x);
    r.y = fmaf(wz0, az.y, wz1 * bz.y);
    r.z = fmaf(wz0, az.z, wz1 * bz.z);
    r.w = fmaf(wz0, az.w, wz1 * bz.w);

    // out float4 index == gid (voxel*2 + chalf) -> 512B/warp coalesced
    ((float4*)out)[gid] = r;
}

extern "C" void kernel_launch(void* const* d_in, const int* in_sizes, int n_in,
                              void* d_out, int out_size)
{
    const float* fmap  = (const float*)d_in[0];
    const float* theta = (const float*)d_in[1];
    float* out = (float*)d_out;

    const int total = RS_B * RS_P * RS_VOX * 2;   // 8,388,608 threads
    resample_kernel<<<total / 256, 256>>>(fmap, theta, out);
}

// round 12
// speedup vs baseline: 1.0373x; 1.0373x over previous
#include <cuda_runtime.h>

// Resampling: 3D affine grid-sample, trilinear, fp32.
// fmap (B=16,P=8,H=32,W=32,D=32,C=8), theta (B,12*P).
//
// 2 lanes per voxel (channel-half split), 16 voxels/warp — R11 mapping,
// which measured L1-wavefront-bound (87%) at occ 61%. This round forces
// 32 regs via __launch_bounds__(256,8) for full 64-warp occupancy; corner
// loads issued in two waves of 4 (z0 wave -> az, z1 wave -> bz) to halve
// peak live registers and avoid spills.

#define RS_B 16
#define RS_P 8
#define RS_H 32
#define RS_W 32
#define RS_D 32
#define RS_C 8
#define RS_VOX (RS_H * RS_W * RS_D)   // 32768 voxels per (b,p) slice

__global__ __launch_bounds__(256, 8) void resample_kernel(
    const float* __restrict__ fmap,
    const float* __restrict__ theta,
    float* __restrict__ out)
{
    __shared__ float t[12];

    const int gid   = blockIdx.x * 256 + threadIdx.x;
    const int voxel = gid >> 1;                 // global voxel id
    const int chalf = gid & 1;                  // which float4 channel half

    const int slice = voxel >> 15;              // b*P + p
    const int n     = voxel & (RS_VOX - 1);

    // theta row: b*96 + p*12 floats — block covers 128 voxels, one slice
    if (threadIdx.x < 12) {
        const int bslice = (blockIdx.x * 128) >> 15;
        t[threadIdx.x] = theta[(bslice >> 3) * (12 * RS_P)
                               + (bslice & (RS_P - 1)) * 12 + threadIdx.x];
    }
    __syncthreads();

    // n = (h*W + w)*D + d ; grid point is (xs[w], ys[h], zs[d])
    const int h = n >> 10;
    const int w = (n >> 5) & 31;
    const int d = n & 31;

    const float step = 2.0f / 31.0f;
    const float gx = fmaf((float)w, step, -1.0f);
    const float gy = fmaf((float)h, step, -1.0f);
    const float gz = fmaf((float)d, step, -1.0f);

    const float xp = t[0] * gx + t[1] * gy + t[2]  * gz + t[3];
    const float yp = t[4] * gx + t[5] * gy + t[6]  * gz + t[7];
    const float zp = t[8] * gx + t[9] * gy + t[10] * gz + t[11];

    const float x = 0.5f * (xp + 1.0f) * (float)(RS_W - 2);
    const float y = 0.5f * (yp + 1.0f) * (float)(RS_H - 2);
    const float z = 0.5f * (zp + 1.0f) * (float)(RS_D - 2);

    int x0 = (int)floorf(x); int x1 = x0 + 1;
    int y0 = (int)floorf(y); int y1 = y0 + 1;
    int z0 = (int)floorf(z); int z1 = z0 + 1;
    x0 = min(max(x0, 0), RS_W - 1); x1 = min(max(x1, 0), RS_W - 1);
    y0 = min(max(y0, 0), RS_H - 1); y1 = min(max(y1, 0), RS_H - 1);
    z0 = min(max(z0, 0), RS_D - 1); z1 = min(max(z1, 0), RS_D - 1);

    // weights from CLAMPED corners (reference semantics)
    const float xd = x - (float)x0;        // weight x1; (1-xd) x0
    const float yd = (float)y1 - y;        // weight y0; (1-yd) y1
    const float zd = z - (float)z0;        // weight z1; (1-zd) z0

    const float wx0 = 1.0f - xd, wx1 = xd;
    const float wy0 = yd,        wy1 = 1.0f - yd;
    const float wz0 = 1.0f - zd, wz1 = zd;

    // lane base: this chalf's float4 at z0 within each corner row
    const float* base = fmap + (size_t)slice * (RS_VOX * RS_C)
                             + (size_t)z0 * RS_C + (size_t)chalf * 4;
    const int dz = (z1 - z0) * 2;          // float4 step to z1 (0 or 2)

    const float w00 = wy0 * wx0;
    const float w01 = wy0 * wx1;
    const float w10 = wy1 * wx0;
    const float w11 = wy1 * wx1;

    const int r00 = (y0 * RS_W + x0) * (RS_D * RS_C);
    const int r01 = (y0 * RS_W + x1) * (RS_D * RS_C);
    const int r10 = (y1 * RS_W + x0) * (RS_D * RS_C);
    const int r11 = (y1 * RS_W + x1) * (RS_D * RS_C);

    const float4* p00 = (const float4*)(base + r00);
    const float4* p01 = (const float4*)(base + r01);
    const float4* p10 = (const float4*)(base + r10);
    const float4* p11 = (const float4*)(base + r11);

    float4 az, bz;   // accumulators for z0 and z1 planes

    // wave 1: z0 corner loads
    {
        const float4 a00 = __ldg(p00);
        const float4 a01 = __ldg(p01);
        const float4 a10 = __ldg(p10);
        const float4 a11 = __ldg(p11);

        az.x = w00 * a00.x; az.y = w00 * a00.y; az.z = w00 * a00.z; az.w = w00 * a00.w;
        az.x = fmaf(w01, a01.x, az.x); az.y = fmaf(w01, a01.y, az.y);
        az.z = fmaf(w01, a01.z, az.z); az.w = fmaf(w01, a01.w, az.w);
        az.x = fmaf(w10, a10.x, az.x); az.y = fmaf(w10, a10.y, az.y);
        az.z = fmaf(w10, a10.z, az.z); az.w = fmaf(w10, a10.w, az.w);
        az.x = fmaf(w11, a11.x, az.x); az.y = fmaf(w11, a11.y, az.y);
        az.z = fmaf(w11, a11.z, az.z); az.w = fmaf(w11, a11.w, az.w);
    }

    // wave 2: z1 corner loads (independent of wave-1 FMAs; ptxas overlaps)
    {
        const float4 b00 = __ldg(p00 + dz);
        const float4 b01 = __ldg(p01 + dz);
        const float4 b10 = __ldg(p10 + dz);
        const float4 b11 = __ldg(p11 + dz);

        bz.x = w00 * b00.x; bz.y = w00 * b00.y; bz.z = w00 * b00.z; bz.w = w00 * b00.w;
        bz.x = fmaf(w01, b01.x, bz.x); bz.y = fmaf(w01, b01.y, bz.y);
        bz.z = fmaf(w01, b01.z, bz.z); bz.w = fmaf(w01, b01.w, bz.w);
        bz.x = fmaf(w10, b10.x, bz.x); bz.y = fmaf(w10, b10.y, bz.y);
        bz.z = fmaf(w10, b10.z, bz.z); bz.w = fmaf(w10, b10.w, bz.w);
        bz.x = fmaf(w11, b11.x, bz.x); bz.y = fmaf(w11, b11.y, bz.y);
        bz.z = fmaf(w11, b11.z, bz.z); bz.w = fmaf(w11, b11.w, bz.w);
    }

    // z-blend in-lane (no shuffles)
    float4 r;
    r.x = fmaf(wz0, az.x, wz1 * bz.x);
    r.y = fmaf(wz0, az.y, wz1 * bz.y);
    r.z = fmaf(wz0, az.z, wz1 * bz.z);
    r.w = fmaf(wz0, az.w, wz1 * bz.w);

    // out float4 index == gid (voxel*2 + chalf) -> 512B/warp coalesced
    ((float4*)out)[gid] = r;
}

extern "C" void kernel_launch(void* const* d_in, const int* in_sizes, int n_in,
                              void* d_out, int out_size)
{
    const float* fmap  = (const float*)d_in[0];
    const float* theta = (const float*)d_in[1];
    float* out = (float*)d_out;

    const int total = RS_B * RS_P * RS_VOX * 2;   // 8,388,608 threads
    resample_kernel<<<total / 256, 256>>>(fmap, theta, out);
}